// round 2
// baseline (speedup 1.0000x reference)
#include <cuda_runtime.h>
#include <cstdint>

#define NTASKS 64
#define NROWS  2048
#define INSZ   512
#define OUTSZ  512

// Scratch (device globals: no allocation allowed in kernel_launch)
__device__ int g_row_order[NROWS];
__device__ int g_task_off[NTASKS + 1];

// ---------------------------------------------------------------------------
// Kernel 1: counting sort of rows by task id. Single block, 256 threads.
// Robust to task_ids being int64 (reference declares int64) or int32 (JAX
// without x64 silently downcasts): for int64 little-endian values < 2^31 the
// odd 32-bit words are all zero; for real int32 data the odd words are random
// task ids in [0,64) — P(all zero) ~ 64^-1024.
// ---------------------------------------------------------------------------
__global__ void sort_rows_kernel(const void* __restrict__ task_ids_raw) {
    __shared__ int counts[NTASKS];
    __shared__ int offs[NTASKS + 1];
    __shared__ int cursor[NTASKS];
    __shared__ int is64;

    const int tid = threadIdx.x;
    if (tid < NTASKS) counts[tid] = 0;
    if (tid == 0) is64 = 1;
    __syncthreads();

    const int* as32 = (const int*)task_ids_raw;
    // Only inspect first 2048 32-bit words (in-bounds for both widths).
    int nz = 0;
    for (int i = tid; i < NROWS / 2; i += blockDim.x)
        if (as32[2 * i + 1] != 0) nz = 1;
    if (nz) atomicExch(&is64, 0);
    __syncthreads();
    const int wide = is64;

    for (int i = tid; i < NROWS; i += blockDim.x) {
        int t = wide ? as32[2 * i] : as32[i];
        atomicAdd(&counts[t], 1);
    }
    __syncthreads();

    if (tid == 0) {
        int s = 0;
        for (int t = 0; t < NTASKS; t++) { offs[t] = s; cursor[t] = s; s += counts[t]; }
        offs[NTASKS] = s;
    }
    __syncthreads();

    if (tid <= NTASKS) g_task_off[tid] = offs[tid];

    for (int i = tid; i < NROWS; i += blockDim.x) {
        int t = wide ? as32[2 * i] : as32[i];
        int p = atomicAdd(&cursor[t], 1);
        g_row_order[p] = i;
    }
}

// ---------------------------------------------------------------------------
// Kernel 2: per-task GEMM. grid = (OUT/128 = 4, NTASKS = 64), 256 threads.
// Block tile: up to 32 rows x 128 cols, K-tile = 64 through SMEM.
// Thread tile: 4 rows x 4 cols, accumulated as packed f32x2 pairs via
// fma.rn.f32x2 (2 FMAs per issued instruction on the fma pipe).
// Each W element is read from HBM exactly once across the whole grid.
// ---------------------------------------------------------------------------
__global__ __launch_bounds__(256, 2)
void task_gemm_kernel(const float* __restrict__ X,
                      const float* __restrict__ W,
                      float* __restrict__ Out) {
    __shared__ __align__(16) float Xs[32][64];
    __shared__ __align__(16) float Ws[64][128];

    const int t    = blockIdx.y;
    const int col0 = blockIdx.x * 128;
    const int r0   = g_task_off[t];
    const int r1   = g_task_off[t + 1];
    if (r0 >= r1) return;

    const int tid = threadIdx.x;
    const int tc  = tid & 31;   // column group: cols col0 + tc*4 .. +3
    const int tr  = tid >> 5;   // row group: rows tr*4 .. +3

    const float* __restrict__ Wt = W + (size_t)t * INSZ * OUTSZ;

    for (int rowbase = r0; rowbase < r1; rowbase += 32) {
        const int nrows = min(32, r1 - rowbase);

        unsigned long long acc[4][2];
        #pragma unroll
        for (int r = 0; r < 4; r++) { acc[r][0] = 0ull; acc[r][1] = 0ull; }

        for (int kt = 0; kt < INSZ; kt += 64) {
            // --- load X tile: 32 rows x 64 cols (2048 floats, 8 per thread) ---
            {
                const int lr = tid >> 3;            // 0..31
                const int lc = (tid & 7) * 8;       // 0,8,...,56
                float4 v0, v1;
                if (lr < nrows) {
                    const int grow = g_row_order[rowbase + lr];
                    const float4* src =
                        (const float4*)(X + (size_t)grow * INSZ + kt + lc);
                    v0 = src[0]; v1 = src[1];
                } else {
                    v0 = make_float4(0.f, 0.f, 0.f, 0.f); v1 = v0;
                }
                *(float4*)&Xs[lr][lc]     = v0;
                *(float4*)&Xs[lr][lc + 4] = v1;
            }
            // --- load W tile: 64 x 128 floats (8192 floats, 8 float4/thread) ---
            #pragma unroll
            for (int p = 0; p < 8; p++) {
                const int f4   = tid + p * 256;
                const int wrow = f4 >> 5;
                const int wcol = (f4 & 31) << 2;
                *(float4*)&Ws[wrow][wcol] =
                    *(const float4*)(Wt + (size_t)(kt + wrow) * OUTSZ + col0 + wcol);
            }
            __syncthreads();

            #pragma unroll 8
            for (int i = 0; i < 64; i++) {
                // two packed f32x2 weight pairs for this thread's 4 columns
                const ulonglong2 w2 = *(const ulonglong2*)&Ws[i][tc * 4];
                #pragma unroll
                for (int r = 0; r < 4; r++) {
                    const unsigned int xb = __float_as_uint(Xs[tr * 4 + r][i]);
                    unsigned long long xx;
                    asm("mov.b64 %0, {%1, %1};" : "=l"(xx) : "r"(xb));
                    asm("fma.rn.f32x2 %0, %1, %2, %0;"
                        : "+l"(acc[r][0]) : "l"(xx), "l"(w2.x));
                    asm("fma.rn.f32x2 %0, %1, %2, %0;"
                        : "+l"(acc[r][1]) : "l"(xx), "l"(w2.y));
                }
            }
            __syncthreads();
        }

        // --- store: each thread owns 4 rows x 4 cols ---
        #pragma unroll
        for (int r = 0; r < 4; r++) {
            const int lr = tr * 4 + r;
            if (lr < nrows) {
                const int grow = g_row_order[rowbase + lr];
                unsigned int a0, a1, a2, a3;
                asm("mov.b64 {%0, %1}, %2;" : "=r"(a0), "=r"(a1) : "l"(acc[r][0]));
                asm("mov.b64 {%0, %1}, %2;" : "=r"(a2), "=r"(a3) : "l"(acc[r][1]));
                float4 o;
                o.x = __uint_as_float(a0);
                o.y = __uint_as_float(a1);
                o.z = __uint_as_float(a2);
                o.w = __uint_as_float(a3);
                *(float4*)(Out + (size_t)grow * OUTSZ + col0 + tc * 4) = o;
            }
        }
    }
}

extern "C" void kernel_launch(void* const* d_in, const int* in_sizes, int n_in,
                              void* d_out, int out_size) {
    const float* X        = (const float*)d_in[0];   // [2048, 512] fp32
    const void*  task_ids = d_in[1];                 // [2048] int64 (or int32)
    const float* W        = (const float*)d_in[2];   // [64, 512, 512] fp32
    float*       Out      = (float*)d_out;           // [2048, 512] fp32

    sort_rows_kernel<<<1, 256>>>(task_ids);
    dim3 grid(OUTSZ / 128, NTASKS);
    task_gemm_kernel<<<grid, 256>>>(X, W, Out);
}

// round 4
// speedup vs baseline: 2.0000x; 2.0000x over previous
#include <cuda_runtime.h>
#include <cstdint>

#define NTASKS 64
#define NROWS  2048
#define INSZ   512
#define OUTSZ  512
#define MT     64          // M rows per chunk / CTA tile
#define NTILE  256         // N cols per CTA
#define KT     64          // K per stage tile
#define THREADS 512
#define MAXCHUNK 96        // sum ceil(rows_t/64) <= 32 + 63 + 1 <= 96

// SMEM stage layout (bytes). Rows padded +16B for conflict-free ldmatrix.
#define ASTRIDE_B 144      // 64 bf16 cols * 2 + 16 pad
#define BSTRIDE_B 528      // 256 bf16 cols * 2 + 16 pad
#define AH 0
#define AL 9216            // 64*144
#define BH 18432
#define BL 52224           // 18432 + 64*528
#define STAGE 86016        // 52224 + 33792
#define SMEM_TOTAL (2 * STAGE)   // 172032 B

__device__ int g_row_order[NROWS];
__device__ int g_task_off[NTASKS + 1];
__device__ int g_chunk_task[MAXCHUNK];
__device__ int g_chunk_base[MAXCHUNK];
__device__ int g_nchunks;

// ---------------- helpers ----------------
__device__ __forceinline__ uint32_t smem_u32(const void* p) {
    uint32_t a;
    asm("{ .reg .u64 t; cvta.to.shared.u64 t, %1; cvt.u32.u64 %0, t; }" : "=r"(a) : "l"(p));
    return a;
}
__device__ __forceinline__ void sts64(uint32_t a, uint32_t x, uint32_t y) {
    asm volatile("st.shared.v2.b32 [%0], {%1,%2};" :: "r"(a), "r"(x), "r"(y) : "memory");
}
__device__ __forceinline__ uint32_t hi2(float x0, float x1) {  // {bf16(x0) lo, bf16(x1) hi} trunc
    uint32_t d;
    asm("prmt.b32 %0, %1, %2, 0x7632;" : "=r"(d) : "r"(__float_as_uint(x0)), "r"(__float_as_uint(x1)));
    return d;
}
__device__ __forceinline__ uint32_t lo2(float x0, float x1) {  // packed bf16 residuals
    float h0 = __uint_as_float(__float_as_uint(x0) & 0xFFFF0000u);
    float h1 = __uint_as_float(__float_as_uint(x1) & 0xFFFF0000u);
    float l0 = x0 - h0, l1 = x1 - h1;
    uint32_t d;
    asm("cvt.rn.bf16x2.f32 %0, %1, %2;" : "=r"(d) : "f"(l1), "f"(l0));  // upper=l1, lower=l0
    return d;
}
__device__ __forceinline__ void ldm_x4(uint32_t* r, uint32_t a) {
    asm volatile("ldmatrix.sync.aligned.m8n8.x4.shared.b16 {%0,%1,%2,%3}, [%4];"
                 : "=r"(r[0]), "=r"(r[1]), "=r"(r[2]), "=r"(r[3]) : "r"(a));
}
__device__ __forceinline__ void ldm_x4t(uint32_t* r, uint32_t a) {
    asm volatile("ldmatrix.sync.aligned.m8n8.x4.trans.shared.b16 {%0,%1,%2,%3}, [%4];"
                 : "=r"(r[0]), "=r"(r[1]), "=r"(r[2]), "=r"(r[3]) : "r"(a));
}
__device__ __forceinline__ void mma16816(float* c, const uint32_t* a, const uint32_t* b) {
    asm volatile("mma.sync.aligned.m16n8k16.row.col.f32.bf16.bf16.f32 "
                 "{%0,%1,%2,%3}, {%4,%5,%6,%7}, {%8,%9}, {%0,%1,%2,%3};"
                 : "+f"(c[0]), "+f"(c[1]), "+f"(c[2]), "+f"(c[3])
                 : "r"(a[0]), "r"(a[1]), "r"(a[2]), "r"(a[3]), "r"(b[0]), "r"(b[1]));
}

// ---------------------------------------------------------------------------
// Kernel 1: counting sort by task + chunk list.
// ---------------------------------------------------------------------------
__global__ void sort_rows_kernel(const void* __restrict__ task_ids_raw) {
    __shared__ int counts[NTASKS], offs[NTASKS + 1], cursor[NTASKS];
    __shared__ int is64;
    const int tid = threadIdx.x;
    if (tid < NTASKS) counts[tid] = 0;
    if (tid == 0) is64 = 1;
    __syncthreads();
    const int* as32 = (const int*)task_ids_raw;
    int nz = 0;
    for (int i = tid; i < NROWS / 2; i += blockDim.x)
        if (as32[2 * i + 1] != 0) nz = 1;
    if (nz) atomicExch(&is64, 0);
    __syncthreads();
    const int wide = is64;
    for (int i = tid; i < NROWS; i += blockDim.x)
        atomicAdd(&counts[wide ? as32[2 * i] : as32[i]], 1);
    __syncthreads();
    if (tid == 0) {
        int s = 0;
        for (int t = 0; t < NTASKS; t++) { offs[t] = s; cursor[t] = s; s += counts[t]; }
        offs[NTASKS] = s;
        int c = 0;
        for (int t = 0; t < NTASKS; t++)
            for (int b = offs[t]; b < offs[t + 1]; b += MT) {
                g_chunk_task[c] = t; g_chunk_base[c] = b; c++;
            }
        g_nchunks = c;
    }
    __syncthreads();
    if (tid <= NTASKS) g_task_off[tid] = offs[tid];
    for (int i = tid; i < NROWS; i += blockDim.x) {
        int t = wide ? as32[2 * i] : as32[i];
        g_row_order[atomicAdd(&cursor[t], 1)] = i;
    }
}

// ---------------------------------------------------------------------------
// Kernel 2: bf16 hi/lo split GEMM via ldmatrix + mma.sync.m16n8k16.
// grid = (2, 96), 512 threads. CTA tile 64m x 256n, K double-buffered.
// ---------------------------------------------------------------------------
struct Pref { float4 pa0, pa1, pb[8]; };

__global__ __launch_bounds__(THREADS, 1)
void task_gemm_mma(const float* __restrict__ X, const float* __restrict__ W,
                   float* __restrict__ Out) {
    extern __shared__ __align__(16) char smem[];
    const uint32_t sb = smem_u32(smem);

    const int cid = blockIdx.y;
    if (cid >= g_nchunks) return;
    const int t     = g_chunk_task[cid];
    const int base  = g_chunk_base[cid];
    const int nrows = min(MT, g_task_off[t + 1] - base);
    const int col0  = blockIdx.x * NTILE;

    const int tid = threadIdx.x, lane = tid & 31, wid = tid >> 5;
    const int mload = tid >> 3;       // 0..63 : A row / B k-row for loading
    const int c8    = tid & 7;        // f4 lane within row

    const float* __restrict__ Wt = W + (size_t)t * INSZ * OUTSZ + col0;
    const bool avalid = mload < nrows;
    const float* __restrict__ aptr =
        avalid ? (X + (size_t)g_row_order[base + mload] * INSZ) : X;

    Pref p;

    auto ldg_tile = [&](int kt) {
        if (avalid) {
            p.pa0 = *(const float4*)(aptr + kt * KT + c8 * 4);
            p.pa1 = *(const float4*)(aptr + kt * KT + (c8 + 8) * 4);
        }
        const float* br = Wt + (size_t)(kt * KT + mload) * OUTSZ;
        #pragma unroll
        for (int j = 0; j < 8; j++)
            p.pb[j] = *(const float4*)(br + (c8 + 8 * j) * 4);
    };
    auto sts_tile = [&](int s) {
        const uint32_t stg = sb + s * STAGE;
        float4 a0 = p.pa0, a1 = p.pa1;
        if (!avalid) { a0 = make_float4(0.f, 0.f, 0.f, 0.f); a1 = a0; }
        const uint32_t ao = stg + mload * ASTRIDE_B + c8 * 8;
        sts64(ao + AH,      hi2(a0.x, a0.y), hi2(a0.z, a0.w));
        sts64(ao + AH + 64, hi2(a1.x, a1.y), hi2(a1.z, a1.w));
        sts64(ao + AL,      lo2(a0.x, a0.y), lo2(a0.z, a0.w));
        sts64(ao + AL + 64, lo2(a1.x, a1.y), lo2(a1.z, a1.w));
        const uint32_t bo = stg + mload * BSTRIDE_B;
        #pragma unroll
        for (int j = 0; j < 8; j++) {
            const uint32_t fo = bo + (c8 + 8 * j) * 8;
            sts64(fo + BH, hi2(p.pb[j].x, p.pb[j].y), hi2(p.pb[j].z, p.pb[j].w));
            sts64(fo + BL, lo2(p.pb[j].x, p.pb[j].y), lo2(p.pb[j].z, p.pb[j].w));
        }
    };

    // compute-role coords: 16 warps = 2m x 8n, warp tile 32m x 32n
    const int m0w = (wid & 1) * 32;
    const int n0w = (wid >> 1) * 32;
    const int lr  = lane & 15;        // ldmatrix row lane
    const int lc8 = (lane >> 4) * 8;  // ldmatrix col-half

    float acc[2][4][4];
    #pragma unroll
    for (int i = 0; i < 2; i++)
        #pragma unroll
        for (int j = 0; j < 4; j++)
            #pragma unroll
            for (int q = 0; q < 4; q++) acc[i][j][q] = 0.f;

    ldg_tile(0);
    sts_tile(0);
    __syncthreads();

    #pragma unroll 2
    for (int kt = 0; kt < INSZ / KT; kt++) {
        if (kt < 7) ldg_tile(kt + 1);

        const uint32_t stg = sb + (kt & 1) * STAGE;
        #pragma unroll
        for (int ks = 0; ks < 4; ks++) {
            const int k0 = ks * 16;
            uint32_t ah[2][4], al[2][4], bh[2][4], bl[2][4];
            #pragma unroll
            for (int mt = 0; mt < 2; mt++) {
                const uint32_t aoff =
                    stg + (m0w + mt * 16 + lr) * ASTRIDE_B + (k0 + lc8) * 2;
                ldm_x4(ah[mt], aoff + AH);
                ldm_x4(al[mt], aoff + AL);
            }
            #pragma unroll
            for (int nc = 0; nc < 2; nc++) {
                const uint32_t boff =
                    stg + (k0 + lr) * BSTRIDE_B + (n0w + nc * 16 + lc8) * 2;
                ldm_x4t(bh[nc], boff + BH);
                ldm_x4t(bl[nc], boff + BL);
            }
            #pragma unroll
            for (int mt = 0; mt < 2; mt++)
                #pragma unroll
                for (int nc = 0; nc < 2; nc++)
                    #pragma unroll
                    for (int h = 0; h < 2; h++) {
                        const int nf = nc * 2 + h;
                        mma16816(acc[mt][nf], ah[mt], &bh[nc][h * 2]);
                        mma16816(acc[mt][nf], al[mt], &bh[nc][h * 2]);
                        mma16816(acc[mt][nf], ah[mt], &bl[nc][h * 2]);
                    }
        }
        if (kt < 7) sts_tile((kt + 1) & 1);
        __syncthreads();
    }

    // epilogue: C frag (m16n8): c0,c1 @ (row=lane/4, col=2*(lane%4)); c2,c3 @ row+8
    const int er = lane >> 2;
    const int ec = (lane & 3) * 2;
    #pragma unroll
    for (int mt = 0; mt < 2; mt++) {
        const int ml0 = m0w + mt * 16 + er;
        const int ml1 = ml0 + 8;
        const int o0 = (ml0 < nrows) ? g_row_order[base + ml0] : -1;
        const int o1 = (ml1 < nrows) ? g_row_order[base + ml1] : -1;
        #pragma unroll
        for (int nf = 0; nf < 4; nf++) {
            const int col = col0 + n0w + nf * 8 + ec;
            if (o0 >= 0) {
                float2 v = make_float2(acc[mt][nf][0], acc[mt][nf][1]);
                *(float2*)(Out + (size_t)o0 * OUTSZ + col) = v;
            }
            if (o1 >= 0) {
                float2 v = make_float2(acc[mt][nf][2], acc[mt][nf][3]);
                *(float2*)(Out + (size_t)o1 * OUTSZ + col) = v;
            }
        }
    }
}

extern "C" void kernel_launch(void* const* d_in, const int* in_sizes, int n_in,
                              void* d_out, int out_size) {
    const float* X        = (const float*)d_in[0];   // [2048, 512] fp32
    const void*  task_ids = d_in[1];                 // [2048] int64 (or int32)
    const float* W        = (const float*)d_in[2];   // [64, 512, 512] fp32
    float*       Out      = (float*)d_out;           // [2048, 512] fp32

    cudaFuncSetAttribute(task_gemm_mma, cudaFuncAttributeMaxDynamicSharedMemorySize, SMEM_TOTAL);
    sort_rows_kernel<<<1, 256>>>(task_ids);
    dim3 grid(OUTSZ / NTILE, MAXCHUNK);
    task_gemm_mma<<<grid, THREADS, SMEM_TOTAL>>>(X, W, Out);
}